// round 3
// baseline (speedup 1.0000x reference)
#include <cuda_runtime.h>
#include <cuda_fp16.h>
#include <stdint.h>

#define NODES 50000
#define DD 64

// ---------------- scratch (no allocations allowed) ----------------
__device__ __align__(16) __half g_ha[NODES * DD];  // fp16: x@W1[0:64]+b1  (dst half)
__device__ __align__(16) __half g_hb[NODES * DD];  // fp16: x@W1[64:128]   (src half)
__device__ __align__(16) float  g_S[NODES * DD];   // sum of relu(ha[dst]+hb[src])
__device__ __align__(16) float  g_aggr[NODES * DD];
__device__ __align__(16) float  g_hid[NODES * DD];
__device__ __align__(16) float  g_deg[NODES];
__device__ int g_is64;

// ---------------- edge_index dtype detection ----------------
__global__ void detect_kernel(const void* __restrict__ idx) {
    const int* p = (const int*)idx;
    int is64 = 1;
    for (int i = 0; i < 16; i++) {
        int lo = p[2 * i], hi = p[2 * i + 1];
        if (hi != 0 || lo < 0 || lo >= NODES) is64 = 0;
    }
    g_is64 = is64;
}

// ---------------- zero accumulators ----------------
__global__ void zero_kernel() {
    int i = blockIdx.x * blockDim.x + threadIdx.x;
    int stride = gridDim.x * blockDim.x;
    for (int j = i; j < NODES * DD; j += stride) g_S[j] = 0.0f;
    for (int j = i; j < NODES; j += stride) g_deg[j] = 0.0f;
}

// ================= WIDE GEMM: [ha|hb] = x @ [W1a|W1b] (+b1 on ha), fp16 out =================
// BM=128 rows, BN=128 cols, 256 threads, 8x8 outputs/thread. 1 B/FMA LDS.
__global__ __launch_bounds__(256) void gemm_wide(
    const float* __restrict__ x, const float* __restrict__ W1,
    const float* __restrict__ b1, int n)
{
    extern __shared__ float sm[];
    float* xT = sm;             // [64][132]  xT[k][r]
    float* Ws = sm + 64 * 132;  // [64][132]  Ws[k][cc] cc<64->ha cols, cc>=64->hb cols

    const int tid = threadIdx.x;
    const int row0 = blockIdx.x * 128;

    // W1 is [128][64]: rows 0..63 feed ha columns, rows 64..127 feed hb columns
    for (int i = tid; i < 2048; i += 256) {
        int kk = i >> 4, c4 = (i & 15) * 4;
        float4 v = *(const float4*)(W1 + kk * 64 + c4);
        int k = kk & 63;
        int cc = (kk < 64) ? c4 : (64 + c4);
        *(float4*)&Ws[k * 132 + cc] = v;
    }
    // x tile transposed
    {
        int r = tid >> 1, ks = (tid & 1) * 32, gr = row0 + r;
#pragma unroll
        for (int q = 0; q < 8; q++) {
            float4 v = make_float4(0.f, 0.f, 0.f, 0.f);
            if (gr < n) v = *(const float4*)(x + (size_t)gr * DD + ks + q * 4);
            int k = ks + q * 4;
            xT[(k + 0) * 132 + r] = v.x;
            xT[(k + 1) * 132 + r] = v.y;
            xT[(k + 2) * 132 + r] = v.z;
            xT[(k + 3) * 132 + r] = v.w;
        }
    }
    __syncthreads();

    const int ty = tid >> 4, tx = tid & 15;
    const int r0 = ty * 8, c0 = tx * 8;

    float acc[8][8] = {};
#pragma unroll 2
    for (int k = 0; k < 64; k++) {
        float a[8], w[8];
        *(float4*)&a[0] = *(const float4*)&xT[k * 132 + r0];
        *(float4*)&a[4] = *(const float4*)&xT[k * 132 + r0 + 4];
        *(float4*)&w[0] = *(const float4*)&Ws[k * 132 + c0];
        *(float4*)&w[4] = *(const float4*)&Ws[k * 132 + c0 + 4];
#pragma unroll
        for (int i = 0; i < 8; i++)
#pragma unroll
            for (int j = 0; j < 8; j++)
                acc[i][j] = fmaf(a[i], w[j], acc[i][j]);
    }

    const bool isA = (c0 < 64);
    float bb[8];
#pragma unroll
    for (int j = 0; j < 8; j++) bb[j] = isA ? b1[c0 + j] : 0.f;

#pragma unroll
    for (int i = 0; i < 8; i++) {
        int gr = row0 + r0 + i;
        if (gr >= n) break;
        union { uint4 u; __half2 h[4]; } cvt;
#pragma unroll
        for (int j = 0; j < 4; j++)
            cvt.h[j] = __floats2half2_rn(acc[i][2 * j] + bb[2 * j],
                                         acc[i][2 * j + 1] + bb[2 * j + 1]);
        __half* dstp = isA ? (g_ha + (size_t)gr * DD + c0)
                           : (g_hb + (size_t)gr * DD + (c0 - 64));
        *(uint4*)dstp = cvt.u;
    }
}

// ================= 64-col GEMM: C = act(A1@W[0] (+A2@W[1]) + bias*rowscale) =================
// BM=256 rows, 256 threads, 8x8 outputs/thread. 1 B/FMA LDS. occ 2 (85KB smem).
__global__ __launch_bounds__(256) void gemm64(
    const float* __restrict__ A1, const float* __restrict__ A2,
    const float* __restrict__ W, const float* __restrict__ bias,
    const float* __restrict__ rowscale, float* __restrict__ C,
    int n, int do_relu)
{
    extern __shared__ float sm[];
    float* As = sm;             // [64][264]
    float* Ws = sm + 64 * 264;  // [64][68]

    const int tid = threadIdx.x;
    const int row0 = blockIdx.x * 256;
    const int ty = tid >> 3, tx = tid & 7;
    const int r0 = ty * 8, c0 = tx * 8;

    float acc[8][8] = {};

    const int npass = (A2 != nullptr) ? 2 : 1;
    for (int pass = 0; pass < npass; pass++) {
        const float* A = pass ? A2 : A1;
        const float* Wp = W + pass * DD * DD;
        if (pass) __syncthreads();  // protect tiles still being read

        for (int i = tid; i < 1024; i += 256) {
            int k = i >> 4, c4 = (i & 15) * 4;
            *(float4*)&Ws[k * 68 + c4] = *(const float4*)(Wp + k * 64 + c4);
        }
        // A tile: 4 threads per row (coalesced 16B chunks), transposed into As
        {
            int rr = tid >> 2, l4 = (tid & 3) * 16;
#pragma unroll
            for (int it = 0; it < 4; it++) {
                int r = rr + it * 64;
                int gr = row0 + r;
#pragma unroll
                for (int q = 0; q < 4; q++) {
                    float4 v = make_float4(0.f, 0.f, 0.f, 0.f);
                    if (gr < n) v = *(const float4*)(A + (size_t)gr * DD + l4 + q * 4);
                    int k = l4 + q * 4;
                    As[(k + 0) * 264 + r] = v.x;
                    As[(k + 1) * 264 + r] = v.y;
                    As[(k + 2) * 264 + r] = v.z;
                    As[(k + 3) * 264 + r] = v.w;
                }
            }
        }
        __syncthreads();

#pragma unroll 2
        for (int k = 0; k < 64; k++) {
            float a[8], w[8];
            *(float4*)&a[0] = *(const float4*)&As[k * 264 + r0];
            *(float4*)&a[4] = *(const float4*)&As[k * 264 + r0 + 4];
            *(float4*)&w[0] = *(const float4*)&Ws[k * 68 + c0];
            *(float4*)&w[4] = *(const float4*)&Ws[k * 68 + c0 + 4];
#pragma unroll
            for (int i = 0; i < 8; i++)
#pragma unroll
                for (int j = 0; j < 8; j++)
                    acc[i][j] = fmaf(a[i], w[j], acc[i][j]);
        }
    }

    float bv[8];
#pragma unroll
    for (int j = 0; j < 8; j++) bv[j] = bias ? bias[c0 + j] : 0.f;

#pragma unroll
    for (int i = 0; i < 8; i++) {
        int gr = row0 + r0 + i;
        if (gr >= n) break;
        const float s = rowscale ? rowscale[gr] : 1.0f;
        float o[8];
#pragma unroll
        for (int j = 0; j < 8; j++) {
            o[j] = acc[i][j] + bv[j] * s;
            if (do_relu) o[j] = fmaxf(o[j], 0.f);
        }
        *(float4*)(C + (size_t)gr * DD + c0) = *(float4*)&o[0];
        *(float4*)(C + (size_t)gr * DD + c0 + 4) = *(float4*)&o[4];
    }
}

// ================= edge scatter: S[dst] += relu(ha[dst]+hb[src]) =================
// 8 threads/edge, each handles 8 fp16 channels (one uint4 per side).
__launch_bounds__(256)
__global__ void edge_kernel(const void* __restrict__ eidx, int E) {
    const int t = blockIdx.x * blockDim.x + threadIdx.x;
    const int e = t >> 3;
    if (e >= E) return;
    const int lane = t & 7;

    int src, dst;
    if (g_is64) {
        const long long* p = (const long long*)eidx;
        src = (int)__ldg(&p[e]);
        dst = (int)__ldg(&p[E + e]);
    } else {
        const int* p = (const int*)eidx;
        src = __ldg(&p[e]);
        dst = __ldg(&p[E + e]);
    }

    union U { uint4 u; __half2 h[4]; } A, B;
    A.u = __ldg((const uint4*)(g_ha + (size_t)dst * DD) + lane);
    B.u = __ldg((const uint4*)(g_hb + (size_t)src * DD) + lane);

    float v[8];
#pragma unroll
    for (int j = 0; j < 4; j++) {
        float2 fa = __half22float2(A.h[j]);
        float2 fb = __half22float2(B.h[j]);
        v[2 * j]     = fmaxf(fa.x + fb.x, 0.f);
        v[2 * j + 1] = fmaxf(fa.y + fb.y, 0.f);
    }

    float* p = g_S + (size_t)dst * DD + lane * 8;
    asm volatile("red.global.add.v4.f32 [%0], {%1, %2, %3, %4};"
                 :: "l"(p), "f"(v[0]), "f"(v[1]), "f"(v[2]), "f"(v[3]) : "memory");
    asm volatile("red.global.add.v4.f32 [%0], {%1, %2, %3, %4};"
                 :: "l"(p + 4), "f"(v[4]), "f"(v[5]), "f"(v[6]), "f"(v[7]) : "memory");

    if (lane == 0) atomicAdd(&g_deg[dst], 1.0f);
}

// ---------------- launch ----------------
extern "C" void kernel_launch(void* const* d_in, const int* in_sizes, int n_in,
                              void* d_out, int out_size) {
    const float* x   = (const float*)d_in[0];
    const void*  eix = d_in[1];
    const float* W1  = (const float*)d_in[2];
    const float* b1  = (const float*)d_in[3];
    const float* W2  = (const float*)d_in[4];
    const float* b2  = (const float*)d_in[5];
    const float* U1  = (const float*)d_in[6];
    const float* ub1 = (const float*)d_in[7];
    const float* U2  = (const float*)d_in[8];
    const float* ub2 = (const float*)d_in[9];
    float* out = (float*)d_out;

    const int n = in_sizes[0] / DD;   // 50000
    const int E = in_sizes[1] / 2;    // 800000

    float *S, *aggr, *hid, *deg;
    cudaGetSymbolAddress((void**)&S,    g_S);
    cudaGetSymbolAddress((void**)&aggr, g_aggr);
    cudaGetSymbolAddress((void**)&hid,  g_hid);
    cudaGetSymbolAddress((void**)&deg,  g_deg);

    const int WIDE_SMEM = 2 * 64 * 132 * 4;             // 67584 B -> occ limited by regs (~2)
    const int G64_SMEM  = (64 * 264 + 64 * 68) * 4;     // 84992 B -> occ 2
    cudaFuncSetAttribute(gemm_wide, cudaFuncAttributeMaxDynamicSharedMemorySize, WIDE_SMEM);
    cudaFuncSetAttribute(gemm64,    cudaFuncAttributeMaxDynamicSharedMemorySize, G64_SMEM);

    detect_kernel<<<1, 1>>>(eix);
    zero_kernel<<<512, 256>>>();

    // ha|hb (fp16) in one launch
    gemm_wide<<<(n + 127) / 128, 256, WIDE_SMEM>>>(x, W1, b1, n);

    // edge phase
    {
        const long long tot = (long long)E * 8;
        const int grid = (int)((tot + 255) / 256);
        edge_kernel<<<grid, 256>>>(eix, E);
    }

    const int nb = (n + 255) / 256;  // 196
    // aggr = S @ W2 + deg*b2
    gemm64<<<nb, 256, G64_SMEM>>>(S, nullptr, W2, b2, deg, aggr, n, 0);
    // hid = relu(x@U1a + aggr@U1b + ub1)
    gemm64<<<nb, 256, G64_SMEM>>>(x, aggr, U1, ub1, nullptr, hid, n, 1);
    // out = hid @ U2 + ub2
    gemm64<<<nb, 256, G64_SMEM>>>(hid, nullptr, U2, ub2, nullptr, out, n, 0);
}